// round 6
// baseline (speedup 1.0000x reference)
#include <cuda_runtime.h>
#include <string.h>

#define BATCH 512
#define INF   512
#define OUTF  100
#define KD    5
#define OKC   500            // OUTF * KD
#define PLANE (OKC * BATCH)  // 256000
#define NZ    16             // split-K factor (K-slice = 32)
#define LOG2E 1.4426950408889634f

typedef unsigned long long u64;

// Split-K partials [z][c][b] (c = o*KD+k), and the reduced M, both *log2e.
__device__ float g_Mp[NZ][PLANE];
__device__ float g_M[PLANE];

// ---- packed f32x2 helpers ----
__device__ __forceinline__ u64 f2add(u64 a, u64 b) {
    u64 r; asm("add.rn.f32x2 %0,%1,%2;" : "=l"(r) : "l"(a), "l"(b)); return r;
}
__device__ __forceinline__ u64 f2fma(u64 a, u64 b, u64 c) {
    u64 r; asm("fma.rn.f32x2 %0,%1,%2,%3;" : "=l"(r) : "l"(a), "l"(b), "l"(c)); return r;
}
__device__ __forceinline__ float2 u2f(u64 v) {
    float2 f; memcpy(&f, &v, 8); return f;
}
__device__ __forceinline__ u64 dup2(float v) {
    float2 f = make_float2(v, v); u64 r; memcpy(&r, &f, 8); return r;
}
__device__ __forceinline__ float ex2_approx(float x) {
    float y; asm("ex2.approx.ftz.f32 %0, %1;" : "=f"(y) : "f"(x)); return y;
}
#define NEGABS_MASK 0x8000000080000000ULL   // OR -> -(|x|) on both halves

// ---------------------------------------------------------------------------
// Kernel 1: split-K GEMM tuned for RESIDENCY.
// Block tile 64m x 64n, BK=16, K-slice 32, 128 threads, thread tile 8m x 4n.
// A transposed in smem (m-pairs natural); B duplicated in smem (zero MOVs).
// grid = (8 n, 8 m, 16 z) = 1024 blocks -> ~8 CTAs/SM resident.
// ---------------------------------------------------------------------------
__global__ void __launch_bounds__(128, 8)
gemm_kernel(const float* __restrict__ X, const float* __restrict__ W) {
    __shared__ __align__(16) float As[2][16][64];    // [buf][kk][m]       8 KB
    __shared__ __align__(16) float Bd[2][16][128];   // [buf][kk][2n dup] 16 KB

    const int tid = threadIdx.x;
    const int tx  = tid & 15;          // 4 n each
    const int ty  = tid >> 4;          // 8 m each (0..7)
    const int n0  = blockIdx.x * 64;
    const int m0  = blockIdx.y * 64;
    const int k0  = blockIdx.z * 32;

    // A loader: row ar (0..63), k-half ah (0/8); stores transposed.
    const int ar = tid >> 1;
    const int ah = (tid & 1) * 8;
    const float* xp = X + (m0 + ar) * INF + k0 + ah;

    // B loader: kk-row bkr (0..15), 8 cols starting at bcl (two float4 quads).
    const int bkr = tid >> 3;
    const int bcl = (tid & 7) * 8;
    const int bc  = n0 + bcl;
    const bool ok0 = bc < OKC;         // quads: 500 % 4 == 0, per-quad validity
    const bool ok1 = bc + 4 < OKC;
    const float* wp = W + (k0 + bkr) * OKC + bc;
    const float4 fz = make_float4(0.f, 0.f, 0.f, 0.f);

    // prologue: k-tile 0 -> buf 0
    float4 a0 = *(const float4*)xp;
    float4 a1 = *(const float4*)(xp + 4);
    float4 b0 = ok0 ? *(const float4*)wp : fz;
    float4 b1 = ok1 ? *(const float4*)(wp + 4) : fz;
    As[0][ah + 0][ar] = a0.x; As[0][ah + 1][ar] = a0.y;
    As[0][ah + 2][ar] = a0.z; As[0][ah + 3][ar] = a0.w;
    As[0][ah + 4][ar] = a1.x; As[0][ah + 5][ar] = a1.y;
    As[0][ah + 6][ar] = a1.z; As[0][ah + 7][ar] = a1.w;
    *(float2*)&Bd[0][bkr][2 * bcl +  0] = make_float2(b0.x, b0.x);
    *(float2*)&Bd[0][bkr][2 * bcl +  2] = make_float2(b0.y, b0.y);
    *(float2*)&Bd[0][bkr][2 * bcl +  4] = make_float2(b0.z, b0.z);
    *(float2*)&Bd[0][bkr][2 * bcl +  6] = make_float2(b0.w, b0.w);
    *(float2*)&Bd[0][bkr][2 * bcl +  8] = make_float2(b1.x, b1.x);
    *(float2*)&Bd[0][bkr][2 * bcl + 10] = make_float2(b1.y, b1.y);
    *(float2*)&Bd[0][bkr][2 * bcl + 12] = make_float2(b1.z, b1.z);
    *(float2*)&Bd[0][bkr][2 * bcl + 14] = make_float2(b1.w, b1.w);
    __syncthreads();

    u64 acc[4][4];                     // [m-pair][n]
    #pragma unroll
    for (int p = 0; p < 4; p++)
        #pragma unroll
        for (int j = 0; j < 4; j++) acc[p][j] = 0ULL;

    #pragma unroll
    for (int kt = 0; kt < 2; kt++) {
        const int cur = kt;
        if (kt == 0) {                 // prefetch k-tile 1
            a0 = *(const float4*)(xp + 16);
            a1 = *(const float4*)(xp + 16 + 4);
            b0 = ok0 ? *(const float4*)(wp + 16 * OKC) : fz;
            b1 = ok1 ? *(const float4*)(wp + 16 * OKC + 4) : fz;
        }
        #pragma unroll
        for (int kk = 0; kk < 16; kk++) {
            ulonglong2 A01 = *(const ulonglong2*)&As[cur][kk][ty * 8];
            ulonglong2 A23 = *(const ulonglong2*)&As[cur][kk][ty * 8 + 4];
            ulonglong2 B01 = *(const ulonglong2*)&Bd[cur][kk][tx * 8];
            ulonglong2 B23 = *(const ulonglong2*)&Bd[cur][kk][tx * 8 + 4];
            acc[0][0] = f2fma(A01.x, B01.x, acc[0][0]);
            acc[1][0] = f2fma(A01.y, B01.x, acc[1][0]);
            acc[2][0] = f2fma(A23.x, B01.x, acc[2][0]);
            acc[3][0] = f2fma(A23.y, B01.x, acc[3][0]);
            acc[0][1] = f2fma(A01.x, B01.y, acc[0][1]);
            acc[1][1] = f2fma(A01.y, B01.y, acc[1][1]);
            acc[2][1] = f2fma(A23.x, B01.y, acc[2][1]);
            acc[3][1] = f2fma(A23.y, B01.y, acc[3][1]);
            acc[0][2] = f2fma(A01.x, B23.x, acc[0][2]);
            acc[1][2] = f2fma(A01.y, B23.x, acc[1][2]);
            acc[2][2] = f2fma(A23.x, B23.x, acc[2][2]);
            acc[3][2] = f2fma(A23.y, B23.x, acc[3][2]);
            acc[0][3] = f2fma(A01.x, B23.y, acc[0][3]);
            acc[1][3] = f2fma(A01.y, B23.y, acc[1][3]);
            acc[2][3] = f2fma(A23.x, B23.y, acc[2][3]);
            acc[3][3] = f2fma(A23.y, B23.y, acc[3][3]);
        }
        if (kt == 0) {                 // stage k-tile 1 -> buf 1
            As[1][ah + 0][ar] = a0.x; As[1][ah + 1][ar] = a0.y;
            As[1][ah + 2][ar] = a0.z; As[1][ah + 3][ar] = a0.w;
            As[1][ah + 4][ar] = a1.x; As[1][ah + 5][ar] = a1.y;
            As[1][ah + 6][ar] = a1.z; As[1][ah + 7][ar] = a1.w;
            *(float2*)&Bd[1][bkr][2 * bcl +  0] = make_float2(b0.x, b0.x);
            *(float2*)&Bd[1][bkr][2 * bcl +  2] = make_float2(b0.y, b0.y);
            *(float2*)&Bd[1][bkr][2 * bcl +  4] = make_float2(b0.z, b0.z);
            *(float2*)&Bd[1][bkr][2 * bcl +  6] = make_float2(b0.w, b0.w);
            *(float2*)&Bd[1][bkr][2 * bcl +  8] = make_float2(b1.x, b1.x);
            *(float2*)&Bd[1][bkr][2 * bcl + 10] = make_float2(b1.y, b1.y);
            *(float2*)&Bd[1][bkr][2 * bcl + 12] = make_float2(b1.z, b1.z);
            *(float2*)&Bd[1][bkr][2 * bcl + 14] = make_float2(b1.w, b1.w);
            __syncthreads();
        }
    }

    // epilogue: store [c][b] scaled by log2e; m-pairs contiguous.
    float* plane = g_Mp[blockIdx.z];
    #pragma unroll
    for (int j = 0; j < 4; j++) {
        int c = n0 + tx * 4 + j;
        if (c < OKC) {
            float2 v0 = u2f(acc[0][j]), v1 = u2f(acc[1][j]);
            float2 v2 = u2f(acc[2][j]), v3 = u2f(acc[3][j]);
            float4 o0 = make_float4(v0.x * LOG2E, v0.y * LOG2E, v1.x * LOG2E, v1.y * LOG2E);
            float4 o1 = make_float4(v2.x * LOG2E, v2.y * LOG2E, v3.x * LOG2E, v3.y * LOG2E);
            *(float4*)&plane[c * BATCH + m0 + ty * 8]     = o0;
            *(float4*)&plane[c * BATCH + m0 + ty * 8 + 4] = o1;
        }
    }
}

// ---------------------------------------------------------------------------
// Kernel 1b: collapse the NZ split-K planes once (L2-resident traffic).
// ---------------------------------------------------------------------------
__global__ void __launch_bounds__(256)
reduce_kernel() {
    const int i = blockIdx.x * 256 + threadIdx.x;      // float4 index
    float4 s = ((const float4*)g_Mp[0])[i];
    #pragma unroll
    for (int z = 1; z < NZ; z++) {
        float4 t = ((const float4*)g_Mp[z])[i];
        s.x += t.x; s.y += t.y; s.z += t.z; s.w += t.w;
    }
    ((float4*)g_M)[i] = s;
}

// ---------------------------------------------------------------------------
// Kernel 2: pairwise, uniform-i / register-j (unchanged from R5).
// grid = (100, 8) = 800 blocks x 256 thr; thread owns j = tid, tid+256.
// ---------------------------------------------------------------------------
__global__ void __launch_bounds__(256)
pairwise_kernel(float* __restrict__ out) {
    const int o  = blockIdx.x;
    const int z  = blockIdx.y;
    const int i0 = z * 64;
    const int tid = threadIdx.x;
    const int j1 = tid, j2 = tid + 256;

    __shared__ __align__(16) float sP[32][12];   // pair q: (M[2q,k],M[2q+1,k]), pad

    const float* base = g_M + o * KD * BATCH;

    #pragma unroll
    for (int idx = tid; idx < 64 * KD; idx += 256) {
        int k = idx >> 6, b = idx & 63;
        sP[b >> 1][2 * k + (b & 1)] = base[k * BATCH + i0 + b];
    }

    u64 nm1[KD], nm2[KD];
    #pragma unroll
    for (int k = 0; k < KD; k++) {
        nm1[k] = dup2(-base[k * BATCH + j1]);
        nm2[k] = dup2(-base[k * BATCH + j2]);
    }
    __syncthreads();

    float acc1a = 0.f, acc1b = 0.f, acc2a = 0.f, acc2b = 0.f;

    #pragma unroll 8
    for (int s = 0; s < 32; s++) {
        const float* row = &sP[s][0];
        ulonglong2 q01 = *(const ulonglong2*)(row);
        ulonglong2 q23 = *(const ulonglong2*)(row + 4);
        u64 p4 = *(const u64*)(row + 8);
        {
            u64 d0 = f2add(q01.x, nm1[0]) | NEGABS_MASK;
            u64 d1 = f2add(q01.y, nm1[1]) | NEGABS_MASK;
            u64 d2 = f2add(q23.x, nm1[2]) | NEGABS_MASK;
            u64 d3 = f2add(q23.y, nm1[3]) | NEGABS_MASK;
            u64 d4 = f2add(p4,    nm1[4]) | NEGABS_MASK;
            u64 t = f2add(f2add(f2add(d0, d1), f2add(d2, d3)), d4);
            float2 tf = u2f(t);
            acc1a += ex2_approx(tf.x);
            acc1b += ex2_approx(tf.y);
        }
        {
            u64 d0 = f2add(q01.x, nm2[0]) | NEGABS_MASK;
            u64 d1 = f2add(q01.y, nm2[1]) | NEGABS_MASK;
            u64 d2 = f2add(q23.x, nm2[2]) | NEGABS_MASK;
            u64 d3 = f2add(q23.y, nm2[3]) | NEGABS_MASK;
            u64 d4 = f2add(p4,    nm2[4]) | NEGABS_MASK;
            u64 t = f2add(f2add(f2add(d0, d1), f2add(d2, d3)), d4);
            float2 tf = u2f(t);
            acc2a += ex2_approx(tf.x);
            acc2b += ex2_approx(tf.y);
        }
    }

    float r1 = acc1a + acc1b;
    float r2 = acc2a + acc2b;
    if ((j1 >> 6) == z) r1 -= 1.0f;
    if ((j2 >> 6) == z) r2 -= 1.0f;
    atomicAdd(&out[j1 * OUTF + o], r1);
    atomicAdd(&out[j2 * OUTF + o], r2);
}

// ---------------------------------------------------------------------------
extern "C" void kernel_launch(void* const* d_in, const int* in_sizes, int n_in,
                              void* d_out, int out_size) {
    const float* x = (const float*)d_in[0];   // [512, 512]
    const float* T = (const float*)d_in[1];   // [512, 100, 5] == [512, 500]
    float* out = (float*)d_out;               // [512, 100]

    cudaMemsetAsync(out, 0, BATCH * OUTF * sizeof(float));

    dim3 ggrid(8, 8, NZ);                     // 1024 blocks
    gemm_kernel<<<ggrid, 128>>>(x, T);

    reduce_kernel<<<PLANE / 4 / 256, 256>>>();  // 250 blocks

    dim3 pgrid(OUTF, 8);                      // 800 blocks
    pairwise_kernel<<<pgrid, 256>>>(out);
}

// round 7
// speedup vs baseline: 1.2382x; 1.2382x over previous
#include <cuda_runtime.h>
#include <string.h>

#define BATCH 512
#define INF   512
#define OUTF  100
#define KD    5
#define OKC   500            // OUTF * KD
#define PLANE (OKC * BATCH)  // 256000
#define NZ    16             // split-K factor (K-slice = 32)
#define LOG2E 1.4426950408889634f

typedef unsigned long long u64;

// Split-K partials [z][c][b] (c = o*KD+k), and the reduced M, both *log2e.
__device__ float g_Mp[NZ][PLANE];
__device__ float g_M[PLANE];

// ---- packed f32x2 helpers ----
__device__ __forceinline__ u64 f2add(u64 a, u64 b) {
    u64 r; asm("add.rn.f32x2 %0,%1,%2;" : "=l"(r) : "l"(a), "l"(b)); return r;
}
__device__ __forceinline__ u64 f2fma(u64 a, u64 b, u64 c) {
    u64 r; asm("fma.rn.f32x2 %0,%1,%2,%3;" : "=l"(r) : "l"(a), "l"(b), "l"(c)); return r;
}
__device__ __forceinline__ float2 u2f(u64 v) {
    float2 f; memcpy(&f, &v, 8); return f;
}
__device__ __forceinline__ u64 dup2(float v) {
    float2 f = make_float2(v, v); u64 r; memcpy(&r, &f, 8); return r;
}
__device__ __forceinline__ float ex2_approx(float x) {
    float y; asm("ex2.approx.ftz.f32 %0, %1;" : "=f"(y) : "f"(x)); return y;
}
#define NEGABS_MASK 0x8000000080000000ULL   // OR -> -(|x|) on both halves

// ---------------------------------------------------------------------------
// Kernel 1: split-K GEMM — reg-dup B (LDS-light) + high residency.
// Block tile 128m x 32n, BK=16, K-slice 32 (2 k-tiles), 128 threads,
// thread tile 8m(4 packed pairs) x 4n. A transposed in smem; B quad read via
// one LDS.128 and duplicated in registers (4 MOVs per kk).
// grid = (16 n, 4 m, 16 z) = 1024 blocks -> ~7 warps/SMSP resident.
// ---------------------------------------------------------------------------
__global__ void __launch_bounds__(128, 4)
gemm_kernel(const float* __restrict__ X, const float* __restrict__ W) {
    __shared__ __align__(16) float As[2][16][128];   // [buf][kk][m]  16 KB
    __shared__ __align__(16) float Bs[2][16][32];    // [buf][kk][n]   4 KB

    const int tid = threadIdx.x;
    const int tx  = tid & 7;           // 4 n each
    const int ty  = tid >> 3;          // 8 m each (0..15)
    const int n0  = blockIdx.x * 32;
    const int m0  = blockIdx.y * 128;
    const int k0  = blockIdx.z * 32;

    // A loader: one 128-elem m-row per thread, 16 k values (4 float4).
    const float* xp = X + (m0 + tid) * INF + k0;

    // B loader: kk-row bkr (0..15), col quad bcl (0..28).
    const int bkr = tid >> 3;
    const int bcl = (tid & 7) * 4;
    const int bc  = n0 + bcl;
    const bool bok = bc < OKC;         // quads 4-aligned, OKC%4==0
    const float* wp = W + (k0 + bkr) * OKC + bc;
    const float4 fz = make_float4(0.f, 0.f, 0.f, 0.f);

    // prologue: k-tile 0 -> buf 0
    float4 av[4];
    #pragma unroll
    for (int q = 0; q < 4; q++) av[q] = *(const float4*)(xp + q * 4);
    float4 bv = bok ? *(const float4*)wp : fz;
    #pragma unroll
    for (int q = 0; q < 4; q++) {
        As[0][q * 4 + 0][tid] = av[q].x;
        As[0][q * 4 + 1][tid] = av[q].y;
        As[0][q * 4 + 2][tid] = av[q].z;
        As[0][q * 4 + 3][tid] = av[q].w;
    }
    *(float4*)&Bs[0][bkr][bcl] = bv;
    __syncthreads();

    u64 acc[4][4];                     // [m-pair][n]
    #pragma unroll
    for (int p = 0; p < 4; p++)
        #pragma unroll
        for (int j = 0; j < 4; j++) acc[p][j] = 0ULL;

    #pragma unroll
    for (int kt = 0; kt < 2; kt++) {
        if (kt == 0) {                 // prefetch k-tile 1
            #pragma unroll
            for (int q = 0; q < 4; q++) av[q] = *(const float4*)(xp + 16 + q * 4);
            bv = bok ? *(const float4*)(wp + 16 * OKC) : fz;
        }
        #pragma unroll
        for (int kk = 0; kk < 16; kk++) {
            ulonglong2 A01 = *(const ulonglong2*)&As[kt][kk][ty * 8];
            ulonglong2 A23 = *(const ulonglong2*)&As[kt][kk][ty * 8 + 4];
            float4 bq = *(const float4*)&Bs[kt][kk][tx * 4];
            u64 bd0 = dup2(bq.x), bd1 = dup2(bq.y);
            u64 bd2 = dup2(bq.z), bd3 = dup2(bq.w);
            acc[0][0] = f2fma(A01.x, bd0, acc[0][0]);
            acc[1][0] = f2fma(A01.y, bd0, acc[1][0]);
            acc[2][0] = f2fma(A23.x, bd0, acc[2][0]);
            acc[3][0] = f2fma(A23.y, bd0, acc[3][0]);
            acc[0][1] = f2fma(A01.x, bd1, acc[0][1]);
            acc[1][1] = f2fma(A01.y, bd1, acc[1][1]);
            acc[2][1] = f2fma(A23.x, bd1, acc[2][1]);
            acc[3][1] = f2fma(A23.y, bd1, acc[3][1]);
            acc[0][2] = f2fma(A01.x, bd2, acc[0][2]);
            acc[1][2] = f2fma(A01.y, bd2, acc[1][2]);
            acc[2][2] = f2fma(A23.x, bd2, acc[2][2]);
            acc[3][2] = f2fma(A23.y, bd2, acc[3][2]);
            acc[0][3] = f2fma(A01.x, bd3, acc[0][3]);
            acc[1][3] = f2fma(A01.y, bd3, acc[1][3]);
            acc[2][3] = f2fma(A23.x, bd3, acc[2][3]);
            acc[3][3] = f2fma(A23.y, bd3, acc[3][3]);
        }
        if (kt == 0) {                 // stage k-tile 1 -> buf 1
            #pragma unroll
            for (int q = 0; q < 4; q++) {
                As[1][q * 4 + 0][tid] = av[q].x;
                As[1][q * 4 + 1][tid] = av[q].y;
                As[1][q * 4 + 2][tid] = av[q].z;
                As[1][q * 4 + 3][tid] = av[q].w;
            }
            *(float4*)&Bs[1][bkr][bcl] = bv;
            __syncthreads();
        }
    }

    // epilogue: store [c][b] scaled by log2e; m-pairs contiguous.
    float* plane = g_Mp[blockIdx.z];
    #pragma unroll
    for (int j = 0; j < 4; j++) {
        int c = n0 + tx * 4 + j;
        if (c < OKC) {
            float2 v0 = u2f(acc[0][j]), v1 = u2f(acc[1][j]);
            float2 v2 = u2f(acc[2][j]), v3 = u2f(acc[3][j]);
            float4 o0 = make_float4(v0.x * LOG2E, v0.y * LOG2E, v1.x * LOG2E, v1.y * LOG2E);
            float4 o1 = make_float4(v2.x * LOG2E, v2.y * LOG2E, v3.x * LOG2E, v3.y * LOG2E);
            *(float4*)&plane[c * BATCH + m0 + ty * 8]     = o0;
            *(float4*)&plane[c * BATCH + m0 + ty * 8 + 4] = o1;
        }
    }
}

// ---------------------------------------------------------------------------
// Kernel 1b: collapse the NZ split-K planes once (L2-resident traffic).
// ---------------------------------------------------------------------------
__global__ void __launch_bounds__(256)
reduce_kernel() {
    const int i = blockIdx.x * 256 + threadIdx.x;      // float4 index
    float4 s = ((const float4*)g_Mp[0])[i];
    #pragma unroll
    for (int z = 1; z < NZ; z++) {
        float4 t = ((const float4*)g_Mp[z])[i];
        s.x += t.x; s.y += t.y; s.z += t.z; s.w += t.w;
    }
    ((float4*)g_M)[i] = s;
}

// ---------------------------------------------------------------------------
// Kernel 2: pairwise, uniform-i / register-j.
// grid = (100, 8) = 800 blocks x 256 thr; thread owns j = tid, tid+256.
// ---------------------------------------------------------------------------
__global__ void __launch_bounds__(256)
pairwise_kernel(float* __restrict__ out) {
    const int o  = blockIdx.x;
    const int z  = blockIdx.y;
    const int i0 = z * 64;
    const int tid = threadIdx.x;
    const int j1 = tid, j2 = tid + 256;

    __shared__ __align__(16) float sP[32][12];   // pair q: (M[2q,k],M[2q+1,k]), pad

    const float* base = g_M + o * KD * BATCH;

    #pragma unroll
    for (int idx = tid; idx < 64 * KD; idx += 256) {
        int k = idx >> 6, b = idx & 63;
        sP[b >> 1][2 * k + (b & 1)] = base[k * BATCH + i0 + b];
    }

    u64 nm1[KD], nm2[KD];
    #pragma unroll
    for (int k = 0; k < KD; k++) {
        nm1[k] = dup2(-base[k * BATCH + j1]);
        nm2[k] = dup2(-base[k * BATCH + j2]);
    }
    __syncthreads();

    float acc1a = 0.f, acc1b = 0.f, acc2a = 0.f, acc2b = 0.f;

    #pragma unroll 8
    for (int s = 0; s < 32; s++) {
        const float* row = &sP[s][0];
        ulonglong2 q01 = *(const ulonglong2*)(row);
        ulonglong2 q23 = *(const ulonglong2*)(row + 4);
        u64 p4 = *(const u64*)(row + 8);
        {
            u64 d0 = f2add(q01.x, nm1[0]) | NEGABS_MASK;
            u64 d1 = f2add(q01.y, nm1[1]) | NEGABS_MASK;
            u64 d2 = f2add(q23.x, nm1[2]) | NEGABS_MASK;
            u64 d3 = f2add(q23.y, nm1[3]) | NEGABS_MASK;
            u64 d4 = f2add(p4,    nm1[4]) | NEGABS_MASK;
            u64 t = f2add(f2add(f2add(d0, d1), f2add(d2, d3)), d4);
            float2 tf = u2f(t);
            acc1a += ex2_approx(tf.x);
            acc1b += ex2_approx(tf.y);
        }
        {
            u64 d0 = f2add(q01.x, nm2[0]) | NEGABS_MASK;
            u64 d1 = f2add(q01.y, nm2[1]) | NEGABS_MASK;
            u64 d2 = f2add(q23.x, nm2[2]) | NEGABS_MASK;
            u64 d3 = f2add(q23.y, nm2[3]) | NEGABS_MASK;
            u64 d4 = f2add(p4,    nm2[4]) | NEGABS_MASK;
            u64 t = f2add(f2add(f2add(d0, d1), f2add(d2, d3)), d4);
            float2 tf = u2f(t);
            acc2a += ex2_approx(tf.x);
            acc2b += ex2_approx(tf.y);
        }
    }

    float r1 = acc1a + acc1b;
    float r2 = acc2a + acc2b;
    if ((j1 >> 6) == z) r1 -= 1.0f;
    if ((j2 >> 6) == z) r2 -= 1.0f;
    atomicAdd(&out[j1 * OUTF + o], r1);
    atomicAdd(&out[j2 * OUTF + o], r2);
}

// ---------------------------------------------------------------------------
extern "C" void kernel_launch(void* const* d_in, const int* in_sizes, int n_in,
                              void* d_out, int out_size) {
    const float* x = (const float*)d_in[0];   // [512, 512]
    const float* T = (const float*)d_in[1];   // [512, 100, 5] == [512, 500]
    float* out = (float*)d_out;               // [512, 100]

    cudaMemsetAsync(out, 0, BATCH * OUTF * sizeof(float));

    dim3 ggrid(16, 4, NZ);                    // 1024 blocks
    gemm_kernel<<<ggrid, 128>>>(x, T);

    reduce_kernel<<<PLANE / 4 / 256, 256>>>();  // 250 blocks

    dim3 pgrid(OUTF, 8);                      // 800 blocks
    pairwise_kernel<<<pgrid, 256>>>(out);
}

// round 8
// speedup vs baseline: 1.3157x; 1.0626x over previous
#include <cuda_runtime.h>

#define BATCH 512
#define INF   512
#define OUTF  100
#define KD    5
#define OKC   500            // OUTF * KD
#define PLANE (OKC * BATCH)  // 256000
#define NZ    8              // split-K factor (K-slice = 64)
#define LOG2E 1.4426950408889634f

typedef unsigned long long u64;

// Split-K partials [z][c][b] (c = o*KD+k), and the reduced M, both *log2e.
__device__ __align__(16) float g_Mp[NZ][PLANE];
__device__ __align__(16) float g_M[PLANE];

// ---- packed f32x2 helpers (asm only -- no memcpy punning) ----
__device__ __forceinline__ u64 f2add(u64 a, u64 b) {
    u64 r; asm("add.rn.f32x2 %0,%1,%2;" : "=l"(r) : "l"(a), "l"(b)); return r;
}
__device__ __forceinline__ u64 f2fma(u64 a, u64 b, u64 c) {
    u64 r; asm("fma.rn.f32x2 %0,%1,%2,%3;" : "=l"(r) : "l"(a), "l"(b), "l"(c)); return r;
}
__device__ __forceinline__ u64 pk(float lo, float hi) {
    u64 r; asm("mov.b64 %0,{%1,%2};" : "=l"(r) : "f"(lo), "f"(hi)); return r;
}
__device__ __forceinline__ void upk(u64 a, float& lo, float& hi) {
    asm("mov.b64 {%0,%1},%2;" : "=f"(lo), "=f"(hi) : "l"(a));
}
__device__ __forceinline__ u64 dup2(float v) { return pk(v, v); }
__device__ __forceinline__ float ex2_approx(float x) {
    float y; asm("ex2.approx.ftz.f32 %0, %1;" : "=f"(y) : "f"(x)); return y;
}
#define NEGABS_MASK 0x8000000080000000ULL   // OR -> -(|x|) on both halves

// ---------------------------------------------------------------------------
// Kernel 1: split-K GEMM -- lean tiles for residency + latency hiding.
// Block tile 64m x 64n, BK=16, K-slice 64 (4 k-tiles, double buffered),
// 256 threads, thread tile 4m(2 u64) x 4n. A transposed in smem; B quad via
// one LDS.128, duplicated in registers (asm pk). 8 FFMA2 per kk per thread.
// grid = (8 n, 8 m, 8 z) = 512 blocks.
// ---------------------------------------------------------------------------
__global__ void __launch_bounds__(256, 3)
gemm_kernel(const float* __restrict__ X, const float* __restrict__ W) {
    __shared__ __align__(16) float As[2][16][64];    // [buf][kk][m]  8 KB
    __shared__ __align__(16) float Bs[2][16][64];    // [buf][kk][n]  8 KB

    const int tid = threadIdx.x;
    const int tx  = tid & 15;          // n quad (4 n each)
    const int ty  = tid >> 4;          // m quad (4 m each)
    const int n0  = blockIdx.x * 64;
    const int m0  = blockIdx.y * 64;
    const int k0  = blockIdx.z * 64;

    // A loader: row ar (0..63), k quad ak (0/4/8/12); stores transposed.
    const int ar = tid >> 2;
    const int ak = (tid & 3) * 4;
    const float* xp = X + (m0 + ar) * INF + k0 + ak;

    // B loader: kk-row bkr (0..15), col quad bcl; OKC % 4 == 0.
    const int bkr = tid >> 4;
    const int bcl = (tid & 15) * 4;
    const int bc  = n0 + bcl;
    const bool bok = bc < OKC;
    const float* wp = W + (k0 + bkr) * OKC + bc;
    const float4 fz = make_float4(0.f, 0.f, 0.f, 0.f);

    // prologue: k-tile 0 -> buf 0
    float4 av = *(const float4*)xp;
    float4 bv = bok ? *(const float4*)wp : fz;
    As[0][ak + 0][ar] = av.x;
    As[0][ak + 1][ar] = av.y;
    As[0][ak + 2][ar] = av.z;
    As[0][ak + 3][ar] = av.w;
    *(float4*)&Bs[0][bkr][bcl] = bv;
    __syncthreads();

    u64 acc[2][4];                     // [m-pair][n]
    #pragma unroll
    for (int p = 0; p < 2; p++)
        #pragma unroll
        for (int j = 0; j < 4; j++) acc[p][j] = 0ULL;

    #pragma unroll
    for (int kt = 0; kt < 4; kt++) {
        const int cur = kt & 1;
        if (kt < 3) {                  // prefetch next k-tile into registers
            av = *(const float4*)(xp + (kt + 1) * 16);
            bv = bok ? *(const float4*)(wp + (kt + 1) * 16 * OKC) : fz;
        }
        #pragma unroll
        for (int kk = 0; kk < 16; kk++) {
            ulonglong2 A = *(const ulonglong2*)&As[cur][kk][ty * 4];
            float4 bq = *(const float4*)&Bs[cur][kk][tx * 4];
            u64 b0 = pk(bq.x, bq.x);
            u64 b1 = pk(bq.y, bq.y);
            u64 b2 = pk(bq.z, bq.z);
            u64 b3 = pk(bq.w, bq.w);
            acc[0][0] = f2fma(A.x, b0, acc[0][0]);
            acc[1][0] = f2fma(A.y, b0, acc[1][0]);
            acc[0][1] = f2fma(A.x, b1, acc[0][1]);
            acc[1][1] = f2fma(A.y, b1, acc[1][1]);
            acc[0][2] = f2fma(A.x, b2, acc[0][2]);
            acc[1][2] = f2fma(A.y, b2, acc[1][2]);
            acc[0][3] = f2fma(A.x, b3, acc[0][3]);
            acc[1][3] = f2fma(A.y, b3, acc[1][3]);
        }
        if (kt < 3) {                  // stage prefetched tile -> other buffer
            const int nxt = cur ^ 1;
            As[nxt][ak + 0][ar] = av.x;
            As[nxt][ak + 1][ar] = av.y;
            As[nxt][ak + 2][ar] = av.z;
            As[nxt][ak + 3][ar] = av.w;
            *(float4*)&Bs[nxt][bkr][bcl] = bv;
            __syncthreads();
        }
    }

    // epilogue: store [c][b] scaled by log2e; 4 m values contiguous.
    float* plane = g_Mp[blockIdx.z];
    #pragma unroll
    for (int j = 0; j < 4; j++) {
        int c = n0 + tx * 4 + j;
        if (c < OKC) {
            float v0, v1, v2, v3;
            upk(acc[0][j], v0, v1);
            upk(acc[1][j], v2, v3);
            float4 o = make_float4(v0 * LOG2E, v1 * LOG2E, v2 * LOG2E, v3 * LOG2E);
            *(float4*)&plane[c * BATCH + m0 + ty * 4] = o;
        }
    }
}

// ---------------------------------------------------------------------------
// Kernel 1b: collapse the NZ split-K planes once (L2-resident traffic).
// ---------------------------------------------------------------------------
__global__ void __launch_bounds__(256)
reduce_kernel() {
    const int i = blockIdx.x * 256 + threadIdx.x;      // float4 index
    float4 s = ((const float4*)g_Mp[0])[i];
    #pragma unroll
    for (int z = 1; z < NZ; z++) {
        float4 t = ((const float4*)g_Mp[z])[i];
        s.x += t.x; s.y += t.y; s.z += t.z; s.w += t.w;
    }
    ((float4*)g_M)[i] = s;
}

// ---------------------------------------------------------------------------
// Kernel 2: pairwise, uniform-i / register-j (R5 design, proven ~14us).
// grid = (100, 8) = 800 blocks x 256 thr; thread owns j = tid, tid+256.
// ---------------------------------------------------------------------------
__global__ void __launch_bounds__(256)
pairwise_kernel(float* __restrict__ out) {
    const int o  = blockIdx.x;
    const int z  = blockIdx.y;
    const int i0 = z * 64;
    const int tid = threadIdx.x;
    const int j1 = tid, j2 = tid + 256;

    __shared__ __align__(16) float sP[32][12];   // pair q: (M[2q,k],M[2q+1,k]), pad

    const float* base = g_M + o * KD * BATCH;

    #pragma unroll
    for (int idx = tid; idx < 64 * KD; idx += 256) {
        int k = idx >> 6, b = idx & 63;
        sP[b >> 1][2 * k + (b & 1)] = base[k * BATCH + i0 + b];
    }

    u64 nm1[KD], nm2[KD];
    #pragma unroll
    for (int k = 0; k < KD; k++) {
        nm1[k] = dup2(-base[k * BATCH + j1]);
        nm2[k] = dup2(-base[k * BATCH + j2]);
    }
    __syncthreads();

    float acc1a = 0.f, acc1b = 0.f, acc2a = 0.f, acc2b = 0.f;

    #pragma unroll 8
    for (int s = 0; s < 32; s++) {
        const float* row = &sP[s][0];
        ulonglong2 q01 = *(const ulonglong2*)(row);
        ulonglong2 q23 = *(const ulonglong2*)(row + 4);
        u64 p4 = *(const u64*)(row + 8);
        {
            u64 d0 = f2add(q01.x, nm1[0]) | NEGABS_MASK;
            u64 d1 = f2add(q01.y, nm1[1]) | NEGABS_MASK;
            u64 d2 = f2add(q23.x, nm1[2]) | NEGABS_MASK;
            u64 d3 = f2add(q23.y, nm1[3]) | NEGABS_MASK;
            u64 d4 = f2add(p4,    nm1[4]) | NEGABS_MASK;
            u64 t = f2add(f2add(f2add(d0, d1), f2add(d2, d3)), d4);
            float tf0, tf1; upk(t, tf0, tf1);
            acc1a += ex2_approx(tf0);
            acc1b += ex2_approx(tf1);
        }
        {
            u64 d0 = f2add(q01.x, nm2[0]) | NEGABS_MASK;
            u64 d1 = f2add(q01.y, nm2[1]) | NEGABS_MASK;
            u64 d2 = f2add(q23.x, nm2[2]) | NEGABS_MASK;
            u64 d3 = f2add(q23.y, nm2[3]) | NEGABS_MASK;
            u64 d4 = f2add(p4,    nm2[4]) | NEGABS_MASK;
            u64 t = f2add(f2add(f2add(d0, d1), f2add(d2, d3)), d4);
            float tf0, tf1; upk(t, tf0, tf1);
            acc2a += ex2_approx(tf0);
            acc2b += ex2_approx(tf1);
        }
    }

    float r1 = acc1a + acc1b;
    float r2 = acc2a + acc2b;
    if ((j1 >> 6) == z) r1 -= 1.0f;
    if ((j2 >> 6) == z) r2 -= 1.0f;
    atomicAdd(&out[j1 * OUTF + o], r1);
    atomicAdd(&out[j2 * OUTF + o], r2);
}

// ---------------------------------------------------------------------------
extern "C" void kernel_launch(void* const* d_in, const int* in_sizes, int n_in,
                              void* d_out, int out_size) {
    const float* x = (const float*)d_in[0];   // [512, 512]
    const float* T = (const float*)d_in[1];   // [512, 100, 5] == [512, 500]
    float* out = (float*)d_out;               // [512, 100]

    cudaMemsetAsync(out, 0, BATCH * OUTF * sizeof(float));

    dim3 ggrid(8, 8, NZ);                     // 512 blocks
    gemm_kernel<<<ggrid, 256>>>(x, T);

    reduce_kernel<<<PLANE / 4 / 256, 256>>>();  // 250 blocks

    dim3 pgrid(OUTF, 8);                      // 800 blocks
    pairwise_kernel<<<pgrid, 256>>>(out);
}